// round 2
// baseline (speedup 1.0000x reference)
#include <cuda_runtime.h>
#include <math.h>

#define NNODES 100000
#define FIN    128
#define HID    128
#define CLS    64

// ---------------- static device scratch (no allocations allowed) ----------------
__device__ float g_h   [(size_t)NNODES * HID];   // x @ W1
__device__ float g_agg1[(size_t)NNODES * HID];   // layer-1 aggregation, then emb (in-place)
__device__ float g_h2  [(size_t)NNODES * CLS];   // emb @ W2
__device__ float g_agg2[(size_t)NNODES * CLS];   // layer-2 aggregation
__device__ float g_dinv[NNODES];
__device__ int   g_deg [NNODES];
__device__ int   g_idx64;                        // 1 if edge_index is int64, 0 if int32

// ---------------- edge-index dtype detection (runs inside the graph, deterministic) ----
__global__ void detect_idx_kernel(const void* __restrict__ ei, int E, int N) {
    if (threadIdx.x != 0 || blockIdx.x != 0) return;
    const long long* p64 = (const long long*)ei;
    int ok = 1;
    for (int i = 0; i < 128 && i < E; i++) {
        long long a = p64[i];
        long long b = p64[(size_t)E + i];
        if (a < 0 || a >= N || b < 0 || b >= N) { ok = 0; break; }
    }
    g_idx64 = ok;
}

__device__ __forceinline__ int fetch_idx(const void* __restrict__ ei, size_t i) {
    if (g_idx64) return (int)((const long long*)ei)[i];
    return ((const int*)ei)[i];
}

// ---------------- zero scratch that must be re-zeroed every call ----------------
__global__ void zero_all_kernel() {
    size_t tid = (size_t)blockIdx.x * blockDim.x + threadIdx.x;
    size_t st  = (size_t)gridDim.x * blockDim.x;
    float4 z = make_float4(0.f, 0.f, 0.f, 0.f);
    float4* a1 = (float4*)g_agg1;  size_t n1 = (size_t)NNODES * HID / 4;
    for (size_t i = tid; i < n1; i += st) a1[i] = z;
    float4* a2 = (float4*)g_agg2;  size_t n2 = (size_t)NNODES * CLS / 4;
    for (size_t i = tid; i < n2; i += st) a2[i] = z;
    int4* dg = (int4*)g_deg;       size_t n3 = NNODES / 4;   // 100000 % 4 == 0
    int4 zi = make_int4(0, 0, 0, 0);
    for (size_t i = tid; i < n3; i += st) dg[i] = zi;
}

// ---------------- degree (in-degree of dst) ----------------
__global__ void deg_kernel(const void* __restrict__ ei, int E, int N) {
    int i = blockIdx.x * blockDim.x + threadIdx.x;
    if (i >= E) return;
    int d = fetch_idx(ei, (size_t)E + i);
    if ((unsigned)d < (unsigned)N) atomicAdd(&g_deg[d], 1);
}

__global__ void dinv_kernel(int N) {
    int i = blockIdx.x * blockDim.x + threadIdx.x;
    if (i < N) g_dinv[i] = rsqrtf((float)(g_deg[i] + 1));  // +1 self-loop
}

// ---------------- SGEMM: C[M,NC] = A[M,128] @ B[128,NC]  (K fixed 128) ----------
// 64x64 tile, 256 threads, 4x4 per-thread microtile, BK=16.
template <int NC>
__global__ __launch_bounds__(256)
void gemm_k128(const float* __restrict__ A, const float* __restrict__ B,
               float* __restrict__ C, int M) {
    __shared__ float As[16][64];
    __shared__ float Bs[16][64];
    const int tx = threadIdx.x & 15, ty = threadIdx.x >> 4;
    const int rowBase = blockIdx.x * 64;
    const int colBase = blockIdx.y * 64;
    const int t = threadIdx.x;
    const int ar = t >> 2, ac4 = t & 3;    // A tile load coords
    const int br = t >> 4, bc4 = t & 15;   // B tile load coords

    float c[4][4] = {};
    for (int k0 = 0; k0 < 128; k0 += 16) {
        float4 av = make_float4(0.f, 0.f, 0.f, 0.f);
        if (rowBase + ar < M)
            av = *(const float4*)&A[(size_t)(rowBase + ar) * 128 + k0 + ac4 * 4];
        As[ac4 * 4 + 0][ar] = av.x;
        As[ac4 * 4 + 1][ar] = av.y;
        As[ac4 * 4 + 2][ar] = av.z;
        As[ac4 * 4 + 3][ar] = av.w;
        *(float4*)&Bs[br][bc4 * 4] =
            *(const float4*)&B[(size_t)(k0 + br) * NC + colBase + bc4 * 4];
        __syncthreads();
#pragma unroll
        for (int k = 0; k < 16; k++) {
            float4 a = *(float4*)&As[k][ty * 4];
            float4 b = *(float4*)&Bs[k][tx * 4];
            float aa[4] = {a.x, a.y, a.z, a.w};
            float bb[4] = {b.x, b.y, b.z, b.w};
#pragma unroll
            for (int i = 0; i < 4; i++)
#pragma unroll
                for (int j = 0; j < 4; j++) c[i][j] += aa[i] * bb[j];
        }
        __syncthreads();
    }
#pragma unroll
    for (int i = 0; i < 4; i++) {
        int r = rowBase + ty * 4 + i;
        if (r < M)
            *(float4*)&C[(size_t)r * NC + colBase + tx * 4] =
                make_float4(c[i][0], c[i][1], c[i][2], c[i][3]);
    }
}

// ---------------- edge scatter, 128 feats: one warp per edge ----------------
__global__ void scatter128(const void* __restrict__ ei, int E, int N) {
    int g = blockIdx.x * blockDim.x + threadIdx.x;
    int e = g >> 5, lane = g & 31;
    if (e >= E) return;
    int s = fetch_idx(ei, e);
    int d = fetch_idx(ei, (size_t)E + e);
    if ((unsigned)s >= (unsigned)N || (unsigned)d >= (unsigned)N) return;
    float nrm = g_dinv[s] * g_dinv[d];
    float4 v = *(const float4*)&g_h[(size_t)s * 128 + lane * 4];
    v.x *= nrm; v.y *= nrm; v.z *= nrm; v.w *= nrm;
    float* out = &g_agg1[(size_t)d * 128 + lane * 4];
    asm volatile("red.global.add.v4.f32 [%0], {%1,%2,%3,%4};"
                 :: "l"(out), "f"(v.x), "f"(v.y), "f"(v.z), "f"(v.w) : "memory");
}

// ---------------- edge scatter, 64 feats: 16 lanes per edge ----------------
__global__ void scatter64(const void* __restrict__ ei, int E, int N) {
    int g = blockIdx.x * blockDim.x + threadIdx.x;
    int e = g >> 4, l16 = g & 15;
    if (e >= E) return;
    int s = fetch_idx(ei, e);
    int d = fetch_idx(ei, (size_t)E + e);
    if ((unsigned)s >= (unsigned)N || (unsigned)d >= (unsigned)N) return;
    float nrm = g_dinv[s] * g_dinv[d];
    float4 v = *(const float4*)&g_h2[(size_t)s * 64 + l16 * 4];
    v.x *= nrm; v.y *= nrm; v.z *= nrm; v.w *= nrm;
    float* out = &g_agg2[(size_t)d * 64 + l16 * 4];
    asm volatile("red.global.add.v4.f32 [%0], {%1,%2,%3,%4};"
                 :: "l"(out), "f"(v.x), "f"(v.y), "f"(v.z), "f"(v.w) : "memory");
}

// ---------------- self-loop + bias + relu; emb in-place into g_agg1 ----------
__global__ void relu_bias_kernel(const float* __restrict__ b1, float* __restrict__ emb_out,
                                 int N) {
    int idx = blockIdx.x * blockDim.x + threadIdx.x;
    if (idx >= N * 128) return;
    int i = idx >> 7, j = idx & 127;
    float di = g_dinv[i];
    float v = g_agg1[idx] + g_h[idx] * di * di + b1[j];
    v = v > 0.f ? v : 0.f;
    g_agg1[idx] = v;
    if (emb_out) emb_out[idx] = v;
}

// ---------------- self-loop + bias + log_softmax over 64 classes -------------
__global__ void final_kernel(const float* __restrict__ b2, float* __restrict__ out, int N) {
    int g = blockIdx.x * blockDim.x + threadIdx.x;
    int i = g >> 5, lane = g & 31;
    if (i >= N) return;
    float di = g_dinv[i];
    float d2 = di * di;
    size_t base = (size_t)i * 64;
    float v0 = g_agg2[base + lane]      + g_h2[base + lane]      * d2 + b2[lane];
    float v1 = g_agg2[base + lane + 32] + g_h2[base + lane + 32] * d2 + b2[lane + 32];
    float m = fmaxf(v0, v1);
#pragma unroll
    for (int o = 16; o > 0; o >>= 1) m = fmaxf(m, __shfl_xor_sync(0xFFFFFFFFu, m, o));
    float s = __expf(v0 - m) + __expf(v1 - m);
#pragma unroll
    for (int o = 16; o > 0; o >>= 1) s += __shfl_xor_sync(0xFFFFFFFFu, s, o);
    float lse = m + logf(s);
    out[base + lane]      = v0 - lse;
    out[base + lane + 32] = v1 - lse;
}

extern "C" void kernel_launch(void* const* d_in, const int* in_sizes, int n_in,
                              void* d_out, int out_size) {
    const float* x  = (const float*)d_in[0];
    const void*  ei = d_in[1];                    // int32 or int64 — detected on device
    const float* W1 = (const float*)d_in[2];
    const float* b1 = (const float*)d_in[3];
    const float* W2 = (const float*)d_in[4];
    const float* b2 = (const float*)d_in[5];
    const int N = in_sizes[0] / FIN;
    const int E = in_sizes[1] / 2;

    float* out_ls  = (float*)d_out;
    float* out_emb = (out_size >= N * (CLS + HID)) ? out_ls + (size_t)N * CLS : nullptr;

    // host-visible addresses of device symbols (pure lookups; capture-safe)
    static float* s_h    = nullptr;
    static float* s_agg1 = nullptr;
    static float* s_h2   = nullptr;
    if (!s_h) {  // pointer caching only; per-call work is identical
        cudaGetSymbolAddress((void**)&s_h,    g_h);
        cudaGetSymbolAddress((void**)&s_agg1, g_agg1);
        cudaGetSymbolAddress((void**)&s_h2,   g_h2);
    }

    const int T = 256;

    // 0) detect edge_index element width (must precede any index use)
    detect_idx_kernel<<<1, 32>>>(ei, E, N);

    // 1) zero agg buffers + degree
    zero_all_kernel<<<1024, T>>>();

    // 2) degree + norm
    deg_kernel<<<(E + T - 1) / T, T>>>(ei, E, N);
    dinv_kernel<<<(N + T - 1) / T, T>>>(N);

    // 3) h = x @ W1
    {
        dim3 grid((N + 63) / 64, HID / 64);
        gemm_k128<HID><<<grid, T>>>(x, W1, s_h, N);
    }

    // 4) scatter layer 1 (warp per edge)
    {
        long long threads = (long long)E * 32;
        scatter128<<<(int)((threads + T - 1) / T), T>>>(ei, E, N);
    }

    // 5) emb = relu(agg1 + h*dinv^2 + b1)  (in-place into g_agg1, mirror to d_out)
    relu_bias_kernel<<<(N * 128 + T - 1) / T, T>>>(b1, out_emb, N);

    // 6) h2 = emb @ W2
    {
        dim3 grid((N + 63) / 64, CLS / 64);
        gemm_k128<CLS><<<grid, T>>>(s_agg1, W2, s_h2, N);
    }

    // 7) scatter layer 2 (16 lanes per edge)
    {
        long long threads = (long long)E * 16;
        scatter64<<<(int)((threads + T - 1) / T), T>>>(ei, E, N);
    }

    // 8) logits + log_softmax
    {
        long long threads = (long long)N * 32;
        final_kernel<<<(int)((threads + T - 1) / T), T>>>(b2, out_ls, N);
    }
}

// round 3
// speedup vs baseline: 1.6491x; 1.6491x over previous
#include <cuda_runtime.h>
#include <math.h>

#define NNODES 100000
#define FIN    128
#define HID    128
#define CLS    64
#define EMAX   2000000

// ---------------- static device scratch (no allocations allowed) ----------------
__device__ float g_h   [(size_t)NNODES * HID];   // x @ W1
__device__ float g_emb [(size_t)NNODES * HID];   // relu(GCN1) output
__device__ float g_h2  [(size_t)NNODES * CLS];   // emb @ W2
__device__ float g_dinv[NNODES];
__device__ int   g_deg [NNODES];
__device__ int   g_incl[NNODES];                 // per-block inclusive scan
__device__ int   g_bsum[256];                    // block sums for scan
__device__ int   g_rowptr[NNODES + 1];
__device__ int   g_cursor[NNODES];
__device__ int   g_csr_src[EMAX];
__device__ int   g_idx64;                        // 1 if edge_index is int64

// ---------------- edge-index dtype detection ----------------
__global__ void detect_idx_kernel(const void* __restrict__ ei, int E, int N) {
    if (threadIdx.x != 0 || blockIdx.x != 0) return;
    const long long* p64 = (const long long*)ei;
    int ok = 1;
    for (int i = 0; i < 128 && i < E; i++) {
        long long a = p64[i];
        long long b = p64[(size_t)E + i];
        if (a < 0 || a >= N || b < 0 || b >= N) { ok = 0; break; }
    }
    g_idx64 = ok;
}

__device__ __forceinline__ int fetch_idx(const void* __restrict__ ei, size_t i) {
    if (g_idx64) return (int)((const long long*)ei)[i];
    return ((const int*)ei)[i];
}

// ---------------- zero degree ----------------
__global__ void zero_deg_kernel(int N) {
    int i = blockIdx.x * blockDim.x + threadIdx.x;
    if (i < N) g_deg[i] = 0;
}

// ---------------- degree (in-degree of dst) ----------------
__global__ void deg_kernel(const void* __restrict__ ei, int E, int N) {
    int i = blockIdx.x * blockDim.x + threadIdx.x;
    if (i >= E) return;
    int d = fetch_idx(ei, (size_t)E + i);
    if ((unsigned)d < (unsigned)N) atomicAdd(&g_deg[d], 1);
}

__global__ void dinv_kernel(int N) {
    int i = blockIdx.x * blockDim.x + threadIdx.x;
    if (i < N) g_dinv[i] = rsqrtf((float)(g_deg[i] + 1));  // +1 self-loop
}

// ---------------- prefix scan over degrees (3 kernels) ----------------
__global__ __launch_bounds__(1024) void scan1_kernel(int N) {
    __shared__ int sh[1024];
    int i = blockIdx.x * 1024 + threadIdx.x;
    int v = (i < N) ? g_deg[i] : 0;
    sh[threadIdx.x] = v;
    __syncthreads();
    for (int off = 1; off < 1024; off <<= 1) {
        int t = (threadIdx.x >= off) ? sh[threadIdx.x - off] : 0;
        __syncthreads();
        sh[threadIdx.x] += t;
        __syncthreads();
    }
    if (i < N) g_incl[i] = sh[threadIdx.x];
    if (threadIdx.x == 1023) g_bsum[blockIdx.x] = sh[1023];
}

__global__ __launch_bounds__(1024) void scan2_kernel(int nb) {
    __shared__ int sh[1024];
    int v = (threadIdx.x < nb) ? g_bsum[threadIdx.x] : 0;
    sh[threadIdx.x] = v;
    __syncthreads();
    for (int off = 1; off < 1024; off <<= 1) {
        int t = (threadIdx.x >= off) ? sh[threadIdx.x - off] : 0;
        __syncthreads();
        sh[threadIdx.x] += t;
        __syncthreads();
    }
    if (threadIdx.x < nb)
        g_bsum[threadIdx.x] = (threadIdx.x == 0) ? 0 : sh[threadIdx.x - 1];  // exclusive
}

__global__ void scan3_kernel(int N) {
    int i = blockIdx.x * blockDim.x + threadIdx.x;
    if (i >= N) return;
    int v = g_incl[i] + g_bsum[i >> 10];   // global inclusive = rowptr[i+1]
    g_rowptr[i + 1] = v;
    g_cursor[i] = v - g_deg[i];            // = rowptr[i]
    if (i == 0) g_rowptr[0] = 0;
}

// ---------------- CSR fill ----------------
__global__ void fill_csr_kernel(const void* __restrict__ ei, int E, int N) {
    int e = blockIdx.x * blockDim.x + threadIdx.x;
    if (e >= E) return;
    int s = fetch_idx(ei, e);
    int d = fetch_idx(ei, (size_t)E + e);
    if ((unsigned)s >= (unsigned)N || (unsigned)d >= (unsigned)N) return;
    int pos = atomicAdd(&g_cursor[d], 1);
    if (pos < EMAX) g_csr_src[pos] = s;
}

// ---------------- SGEMM: C[M,NC] = A[M,128] @ B[128,NC] ----------
template <int NC>
__global__ __launch_bounds__(256)
void gemm_k128(const float* __restrict__ A, const float* __restrict__ B,
               float* __restrict__ C, int M) {
    __shared__ float As[16][64];
    __shared__ float Bs[16][64];
    const int tx = threadIdx.x & 15, ty = threadIdx.x >> 4;
    const int rowBase = blockIdx.x * 64;
    const int colBase = blockIdx.y * 64;
    const int t = threadIdx.x;
    const int ar = t >> 2, ac4 = t & 3;
    const int br = t >> 4, bc4 = t & 15;

    float c[4][4] = {};
    for (int k0 = 0; k0 < 128; k0 += 16) {
        float4 av = make_float4(0.f, 0.f, 0.f, 0.f);
        if (rowBase + ar < M)
            av = *(const float4*)&A[(size_t)(rowBase + ar) * 128 + k0 + ac4 * 4];
        As[ac4 * 4 + 0][ar] = av.x;
        As[ac4 * 4 + 1][ar] = av.y;
        As[ac4 * 4 + 2][ar] = av.z;
        As[ac4 * 4 + 3][ar] = av.w;
        *(float4*)&Bs[br][bc4 * 4] =
            *(const float4*)&B[(size_t)(k0 + br) * NC + colBase + bc4 * 4];
        __syncthreads();
#pragma unroll
        for (int k = 0; k < 16; k++) {
            float4 a = *(float4*)&As[k][ty * 4];
            float4 b = *(float4*)&Bs[k][tx * 4];
            float aa[4] = {a.x, a.y, a.z, a.w};
            float bb[4] = {b.x, b.y, b.z, b.w};
#pragma unroll
            for (int i = 0; i < 4; i++)
#pragma unroll
                for (int j = 0; j < 4; j++) c[i][j] += aa[i] * bb[j];
        }
        __syncthreads();
    }
#pragma unroll
    for (int i = 0; i < 4; i++) {
        int r = rowBase + ty * 4 + i;
        if (r < M)
            *(float4*)&C[(size_t)r * NC + colBase + tx * 4] =
                make_float4(c[i][0], c[i][1], c[i][2], c[i][3]);
    }
}

// ---------------- layer-1 gather: warp per node, fused self-loop+bias+relu ----
__global__ __launch_bounds__(256)
void gather1_kernel(const float* __restrict__ b1, float* __restrict__ emb_out, int N) {
    int warp = (blockIdx.x * blockDim.x + threadIdx.x) >> 5;
    int lane = threadIdx.x & 31;
    if (warp >= N) return;
    const int i = warp;
    const int start = g_rowptr[i], end = g_rowptr[i + 1];
    const float di = g_dinv[i];

    float4 acc = *(const float4*)&g_h[(size_t)i * 128 + lane * 4];
    float d2 = di * di;
    acc.x *= d2; acc.y *= d2; acc.z *= d2; acc.w *= d2;   // self-loop

    for (int base = start; base < end; base += 32) {
        int rem = end - base;
        int cnt = rem < 32 ? rem : 32;
        int   myidx = (lane < cnt) ? g_csr_src[base + lane] : 0;
        float myw   = (lane < cnt) ? di * g_dinv[myidx] : 0.f;
        for (int j = 0; j < cnt; j++) {
            int   s = __shfl_sync(0xFFFFFFFFu, myidx, j);
            float w = __shfl_sync(0xFFFFFFFFu, myw, j);
            float4 v = *(const float4*)&g_h[(size_t)s * 128 + lane * 4];
            acc.x += v.x * w; acc.y += v.y * w; acc.z += v.z * w; acc.w += v.w * w;
        }
    }
    float4 bv = *(const float4*)&b1[lane * 4];
    acc.x = fmaxf(acc.x + bv.x, 0.f);
    acc.y = fmaxf(acc.y + bv.y, 0.f);
    acc.z = fmaxf(acc.z + bv.z, 0.f);
    acc.w = fmaxf(acc.w + bv.w, 0.f);
    *(float4*)&g_emb[(size_t)i * 128 + lane * 4] = acc;
    if (emb_out) *(float4*)&emb_out[(size_t)i * 128 + lane * 4] = acc;
}

// ---------------- layer-2 gather: warp per node, fused bias+log_softmax -------
__global__ __launch_bounds__(256)
void gather2_kernel(const float* __restrict__ b2, float* __restrict__ out, int N) {
    int warp = (blockIdx.x * blockDim.x + threadIdx.x) >> 5;
    int lane = threadIdx.x & 31;
    if (warp >= N) return;
    const int i = warp;
    const int start = g_rowptr[i], end = g_rowptr[i + 1];
    const float di = g_dinv[i];

    float2 acc = *(const float2*)&g_h2[(size_t)i * 64 + lane * 2];
    float d2 = di * di;
    acc.x *= d2; acc.y *= d2;                              // self-loop

    for (int base = start; base < end; base += 32) {
        int rem = end - base;
        int cnt = rem < 32 ? rem : 32;
        int   myidx = (lane < cnt) ? g_csr_src[base + lane] : 0;
        float myw   = (lane < cnt) ? di * g_dinv[myidx] : 0.f;
        for (int j = 0; j < cnt; j++) {
            int   s = __shfl_sync(0xFFFFFFFFu, myidx, j);
            float w = __shfl_sync(0xFFFFFFFFu, myw, j);
            float2 v = *(const float2*)&g_h2[(size_t)s * 64 + lane * 2];
            acc.x += v.x * w; acc.y += v.y * w;
        }
    }
    float2 bv = *(const float2*)&b2[lane * 2];
    acc.x += bv.x; acc.y += bv.y;

    // log_softmax over 64 classes (2 per lane)
    float m = fmaxf(acc.x, acc.y);
#pragma unroll
    for (int o = 16; o > 0; o >>= 1) m = fmaxf(m, __shfl_xor_sync(0xFFFFFFFFu, m, o));
    float sm = __expf(acc.x - m) + __expf(acc.y - m);
#pragma unroll
    for (int o = 16; o > 0; o >>= 1) sm += __shfl_xor_sync(0xFFFFFFFFu, sm, o);
    float lse = m + logf(sm);
    float2 r = make_float2(acc.x - lse, acc.y - lse);
    *(float2*)&out[(size_t)i * 64 + lane * 2] = r;
}

extern "C" void kernel_launch(void* const* d_in, const int* in_sizes, int n_in,
                              void* d_out, int out_size) {
    const float* x  = (const float*)d_in[0];
    const void*  ei = d_in[1];
    const float* W1 = (const float*)d_in[2];
    const float* b1 = (const float*)d_in[3];
    const float* W2 = (const float*)d_in[4];
    const float* b2 = (const float*)d_in[5];
    const int N = in_sizes[0] / FIN;
    const int E = in_sizes[1] / 2;

    float* out_ls  = (float*)d_out;
    float* out_emb = (out_size >= N * (CLS + HID)) ? out_ls + (size_t)N * CLS : nullptr;

    static float* s_h   = nullptr;
    static float* s_emb = nullptr;
    static float* s_h2  = nullptr;
    if (!s_h) {
        cudaGetSymbolAddress((void**)&s_h,   g_h);
        cudaGetSymbolAddress((void**)&s_emb, g_emb);
        cudaGetSymbolAddress((void**)&s_h2,  g_h2);
    }

    const int T = 256;
    const int nScanBlocks = (N + 1023) / 1024;

    // 0) dtype detect + degree + norm
    detect_idx_kernel<<<1, 32>>>(ei, E, N);
    zero_deg_kernel<<<(N + T - 1) / T, T>>>(N);
    deg_kernel<<<(E + T - 1) / T, T>>>(ei, E, N);
    dinv_kernel<<<(N + T - 1) / T, T>>>(N);

    // 1) CSR build (prefix scan + fill)
    scan1_kernel<<<nScanBlocks, 1024>>>(N);
    scan2_kernel<<<1, 1024>>>(nScanBlocks);
    scan3_kernel<<<(N + T - 1) / T, T>>>(N);
    fill_csr_kernel<<<(E + T - 1) / T, T>>>(ei, E, N);

    // 2) h = x @ W1
    {
        dim3 grid((N + 63) / 64, HID / 64);
        gemm_k128<HID><<<grid, T>>>(x, W1, s_h, N);
    }

    // 3) layer-1 gather (fused self-loop + bias + relu) -> emb
    {
        long long threads = (long long)N * 32;
        gather1_kernel<<<(int)((threads + T - 1) / T), T>>>(b1, out_emb, N);
    }

    // 4) h2 = emb @ W2
    {
        dim3 grid((N + 63) / 64, CLS / 64);
        gemm_k128<CLS><<<grid, T>>>(s_emb, W2, s_h2, N);
    }

    // 5) layer-2 gather (fused self-loop + bias + log_softmax) -> out
    {
        long long threads = (long long)N * 32;
        gather2_kernel<<<(int)((threads + T - 1) / T), T>>>(b2, out_ls, N);
    }
}